// round 10
// baseline (speedup 1.0000x reference)
#include <cuda_runtime.h>
#include <cuda_fp16.h>

// Fixed shapes for SPHERE_CUDA_77163382440039
static constexpr int HW  = 512 * 512;   // 262144 HT cells
static constexpr int NCH = 128;         // flat channels (B4 * C4)
static constexpr int S   = 32768;       // sphere bins
static constexpr int CAP = 128;         // bucket capacity per bin (Poisson(45.8))

// Scratch (static __device__ — no runtime allocation).
// g_cursor is zero-initialized at module load; accum_kernel resets each bin's
// cursor to 0 after consuming it, so every kernel_launch (first call and every
// graph replay) starts from all-zero cursors without a dedicated zero kernel.
__device__ __align__(16) __half g_xTh[(size_t)HW * NCH];     // x transposed [hw][ch], fp16, 67 MB
__device__ __align__(16) float2 g_bucket[(size_t)S * CAP];   // (h bits, weight) per bin, 33.5 MB
__device__ int g_cursor[S];

// ---------------------------------------------------------------------------
// FUSED: transpose+convert (x [128][HW] fp32 -> g_xTh [HW][128] fp16) AND
// vote scatter (bucket by sphere bin). The two tasks touch disjoint data;
// per-block interleaving lets the scatter's dependent-chain latency hide
// under the transpose's bandwidth stream.
// Grid: 8192 blocks x 256 thr. Transpose tile = 32 ch x 128 hw per block.
__global__ __launch_bounds__(256) void fused_transpose_scatter_kernel(
    const float* __restrict__ in,
    const int* __restrict__ ht_idx,
    const int* __restrict__ sp_idx,
    const float* __restrict__ weight,
    int nvotes, int vpb) {
    __shared__ float4 tile4[32][32];    // 16 KB, [ch][swizzled hw4]
    const int t  = threadIdx.x;
    const int h0 = (blockIdx.x & 2047) * 128;
    const int r0 = (blockIdx.x >> 11) * 32;

    // Phase 1a: issue transpose global loads (512B warp runs) into registers.
    float4 v0, v1, v2, v3;
    {
        int hw4 = t & 31;
        int c0  = (t >> 5);
        v0 = *reinterpret_cast<const float4*>(&in[(size_t)(r0 + c0 +  0) * HW + h0 + hw4 * 4]);
        v1 = *reinterpret_cast<const float4*>(&in[(size_t)(r0 + c0 +  8) * HW + h0 + hw4 * 4]);
        v2 = *reinterpret_cast<const float4*>(&in[(size_t)(r0 + c0 + 16) * HW + h0 + hw4 * 4]);
        v3 = *reinterpret_cast<const float4*>(&in[(size_t)(r0 + c0 + 24) * HW + h0 + hw4 * 4]);
    }

    // Phase 1b: scatter this block's votes while the loads are in flight.
    {
        int v = blockIdx.x * vpb + t;
        if (t < vpb && v < nvotes) {
            int s   = sp_idx[v];
            int pos = atomicAdd(&g_cursor[s], 1);
            if (pos < CAP) {
                g_bucket[(size_t)s * CAP + pos] =
                    make_float2(__int_as_float(ht_idx[v]), weight[v]);
            }
        }
    }

    // Phase 1c: smem stores at XOR-swizzled column (conflict-free).
    {
        int hw4 = t & 31;
        int c0  = (t >> 5);
        tile4[c0 +  0][hw4 ^ ((((c0 +  0) >> 3) & 3) << 1)] = v0;
        tile4[c0 +  8][hw4 ^ ((((c0 +  8) >> 3) & 3) << 1)] = v1;
        tile4[c0 + 16][hw4 ^ ((((c0 + 16) >> 3) & 3) << 1)] = v2;
        tile4[c0 + 24][hw4 ^ ((((c0 + 24) >> 3) & 3) << 1)] = v3;
    }
    __syncthreads();

    // Phase 2: conflict-free scalar smem reads -> pack 8 halves ->
    // 16B global stores in 64B full-sector runs.
    const float* tf = reinterpret_cast<const float*>(tile4);
    #pragma unroll
    for (int k = 0; k < 2; k++) {
        int chg  = t & 3;                               // group of 8 channels
        int hw_l = (t >> 5) * 8 + ((t & 31) >> 2) + k * 64;
        int swz  = (chg << 1);
        int col  = ((hw_l >> 2) ^ swz) * 4 + (hw_l & 3);
        float f0 = tf[(chg * 8 + 0) * 128 + col];
        float f1 = tf[(chg * 8 + 1) * 128 + col];
        float f2 = tf[(chg * 8 + 2) * 128 + col];
        float f3 = tf[(chg * 8 + 3) * 128 + col];
        float f4 = tf[(chg * 8 + 4) * 128 + col];
        float f5 = tf[(chg * 8 + 5) * 128 + col];
        float f6 = tf[(chg * 8 + 6) * 128 + col];
        float f7 = tf[(chg * 8 + 7) * 128 + col];
        __half2 h0p = __floats2half2_rn(f0, f1);
        __half2 h1p = __floats2half2_rn(f2, f3);
        __half2 h2p = __floats2half2_rn(f4, f5);
        __half2 h3p = __floats2half2_rn(f6, f7);
        uint4 pk;
        pk.x = *reinterpret_cast<const unsigned*>(&h0p);
        pk.y = *reinterpret_cast<const unsigned*>(&h1p);
        pk.z = *reinterpret_cast<const unsigned*>(&h2p);
        pk.w = *reinterpret_cast<const unsigned*>(&h3p);
        *reinterpret_cast<uint4*>(
            &g_xTh[(size_t)(h0 + hw_l) * NCH + r0 + chg * 8]) = pk;
    }
}

// ---------------------------------------------------------------------------
// One warp per sphere bin; lane l owns channels [4l, 4l+4) in fp32 registers.
// R6-proven loop: unroll-8 with float4 record loads (8 gathers in flight),
// short serial tail. 8 bins/block; smem-staged fused output transpose.
// Lane 0 resets this bin's cursor after reading it (replaces zero kernel).
__global__ __launch_bounds__(256) void accum_kernel(float* __restrict__ out) {
    const int warp = threadIdx.x >> 5;
    const int lane = threadIdx.x & 31;
    const int s    = blockIdx.x * 8 + warp;

    int n = g_cursor[s];
    if (lane == 0) g_cursor[s] = 0;     // restore invariant for next launch
    if (n > CAP) n = CAP;
    const float2* __restrict__ rec  = &g_bucket[(size_t)s * CAP];
    const float4* __restrict__ rec4 = reinterpret_cast<const float4*>(rec);
    const size_t col = (size_t)(lane * 4);

    float4 a0 = make_float4(0.f, 0.f, 0.f, 0.f);
    float4 a1 = make_float4(0.f, 0.f, 0.f, 0.f);

    int i = 0;
    for (; i + 8 <= n; i += 8) {
        float4 ra = rec4[(i >> 1) + 0];
        float4 rb = rec4[(i >> 1) + 1];
        float4 rc = rec4[(i >> 1) + 2];
        float4 rd = rec4[(i >> 1) + 3];
        const uint2 p0 = *reinterpret_cast<const uint2*>(
            &g_xTh[(size_t)__float_as_int(ra.x) * NCH + col]);
        const uint2 p1 = *reinterpret_cast<const uint2*>(
            &g_xTh[(size_t)__float_as_int(ra.z) * NCH + col]);
        const uint2 p2 = *reinterpret_cast<const uint2*>(
            &g_xTh[(size_t)__float_as_int(rb.x) * NCH + col]);
        const uint2 p3 = *reinterpret_cast<const uint2*>(
            &g_xTh[(size_t)__float_as_int(rb.z) * NCH + col]);
        const uint2 p4 = *reinterpret_cast<const uint2*>(
            &g_xTh[(size_t)__float_as_int(rc.x) * NCH + col]);
        const uint2 p5 = *reinterpret_cast<const uint2*>(
            &g_xTh[(size_t)__float_as_int(rc.z) * NCH + col]);
        const uint2 p6 = *reinterpret_cast<const uint2*>(
            &g_xTh[(size_t)__float_as_int(rd.x) * NCH + col]);
        const uint2 p7 = *reinterpret_cast<const uint2*>(
            &g_xTh[(size_t)__float_as_int(rd.z) * NCH + col]);

        float2 f;
        f = __half22float2(*reinterpret_cast<const __half2*>(&p0.x));
        a0.x += f.x * ra.y; a0.y += f.y * ra.y;
        f = __half22float2(*reinterpret_cast<const __half2*>(&p0.y));
        a0.z += f.x * ra.y; a0.w += f.y * ra.y;
        f = __half22float2(*reinterpret_cast<const __half2*>(&p1.x));
        a1.x += f.x * ra.w; a1.y += f.y * ra.w;
        f = __half22float2(*reinterpret_cast<const __half2*>(&p1.y));
        a1.z += f.x * ra.w; a1.w += f.y * ra.w;

        f = __half22float2(*reinterpret_cast<const __half2*>(&p2.x));
        a0.x += f.x * rb.y; a0.y += f.y * rb.y;
        f = __half22float2(*reinterpret_cast<const __half2*>(&p2.y));
        a0.z += f.x * rb.y; a0.w += f.y * rb.y;
        f = __half22float2(*reinterpret_cast<const __half2*>(&p3.x));
        a1.x += f.x * rb.w; a1.y += f.y * rb.w;
        f = __half22float2(*reinterpret_cast<const __half2*>(&p3.y));
        a1.z += f.x * rb.w; a1.w += f.y * rb.w;

        f = __half22float2(*reinterpret_cast<const __half2*>(&p4.x));
        a0.x += f.x * rc.y; a0.y += f.y * rc.y;
        f = __half22float2(*reinterpret_cast<const __half2*>(&p4.y));
        a0.z += f.x * rc.y; a0.w += f.y * rc.y;
        f = __half22float2(*reinterpret_cast<const __half2*>(&p5.x));
        a1.x += f.x * rc.w; a1.y += f.y * rc.w;
        f = __half22float2(*reinterpret_cast<const __half2*>(&p5.y));
        a1.z += f.x * rc.w; a1.w += f.y * rc.w;

        f = __half22float2(*reinterpret_cast<const __half2*>(&p6.x));
        a0.x += f.x * rd.y; a0.y += f.y * rd.y;
        f = __half22float2(*reinterpret_cast<const __half2*>(&p6.y));
        a0.z += f.x * rd.y; a0.w += f.y * rd.y;
        f = __half22float2(*reinterpret_cast<const __half2*>(&p7.x));
        a1.x += f.x * rd.w; a1.y += f.y * rd.w;
        f = __half22float2(*reinterpret_cast<const __half2*>(&p7.y));
        a1.z += f.x * rd.w; a1.w += f.y * rd.w;
    }
    for (; i < n; i++) {
        float2 r0 = rec[i];
        const uint2 p0 = *reinterpret_cast<const uint2*>(
            &g_xTh[(size_t)__float_as_int(r0.x) * NCH + col]);
        float2 f;
        f = __half22float2(*reinterpret_cast<const __half2*>(&p0.x));
        a0.x += f.x * r0.y; a0.y += f.y * r0.y;
        f = __half22float2(*reinterpret_cast<const __half2*>(&p0.y));
        a0.z += f.x * r0.y; a0.w += f.y * r0.y;
    }
    a0.x += a1.x; a0.y += a1.y; a0.z += a1.z; a0.w += a1.w;

    // Stage [8 bins][128 ch] in smem, then write out[ch][s0..s0+7] coalesced.
    __shared__ float sm[8][128];
    *reinterpret_cast<float4*>(&sm[warp][lane * 4]) = a0;
    __syncthreads();

    if (threadIdx.x < 128) {
        const int ch = threadIdx.x;
        const int s0 = blockIdx.x * 8;
        float4 o0 = make_float4(sm[0][ch], sm[1][ch], sm[2][ch], sm[3][ch]);
        float4 o1 = make_float4(sm[4][ch], sm[5][ch], sm[6][ch], sm[7][ch]);
        float4* dst = reinterpret_cast<float4*>(&out[(size_t)ch * S + s0]);
        dst[0] = o0;
        dst[1] = o1;
    }
}

// ---------------------------------------------------------------------------
extern "C" void kernel_launch(void* const* d_in, const int* in_sizes, int n_in,
                              void* d_out, int out_size) {
    const float* x      = (const float*)d_in[0];  // [128][262144] flat
    const int*   ht     = (const int*)d_in[1];
    const int*   sp     = (const int*)d_in[2];
    const float* w      = (const float*)d_in[3];
    float*       out    = (float*)d_out;          // [128][32768] flat
    const int    nvotes = in_sizes[1];

    // 1) Fused transpose+convert AND vote scatter. Cursors are guaranteed zero
    //    here: static init on first call, accum_kernel's reset on later calls.
    {
        const int nblocks = 8192;                          // (HW/128) * (NCH/32)
        const int vpb = (nvotes + nblocks - 1) / nblocks;  // 184 <= 256
        fused_transpose_scatter_kernel<<<nblocks, 256>>>(x, ht, sp, w, nvotes, vpb);
    }

    // 2) Per-bin register accumulation (R6-proven loop) + fused output
    //    transpose + cursor reset.
    accum_kernel<<<S / 8, 256>>>(out);
}

// round 11
// speedup vs baseline: 1.5403x; 1.5403x over previous
#include <cuda_runtime.h>
#include <cuda_fp16.h>

// Fixed shapes for SPHERE_CUDA_77163382440039
static constexpr int HW  = 512 * 512;   // 262144 HT cells
static constexpr int NCH = 128;         // flat channels (B4 * C4)
static constexpr int S   = 32768;       // sphere bins
static constexpr int CAP = 128;         // bucket capacity per bin (Poisson(45.8))

// Scratch (static __device__ — no runtime allocation).
// g_cursor is zero-initialized at module load; accum_kernel resets cursors in
// its EPILOGUE (after the hot loop + block barrier), so every kernel_launch
// starts from all-zero cursors without a dedicated zero kernel.
__device__ __align__(16) __half g_xTh[(size_t)HW * NCH];     // x transposed [hw][ch], fp16, 67 MB
__device__ __align__(16) float2 g_bucket[(size_t)S * CAP];   // (h bits, weight) per bin, 33.5 MB
__device__ int g_cursor[S];

// ---------------------------------------------------------------------------
// FUSED: transpose+convert (x [128][HW] fp32 -> g_xTh [HW][128] fp16) AND
// vote scatter (bucket by sphere bin). The two tasks touch disjoint data;
// per-block interleaving lets the scatter's dependent-chain latency hide
// under the transpose's bandwidth stream.
// Grid: 8192 blocks x 256 thr. Transpose tile = 32 ch x 128 hw per block.
__global__ __launch_bounds__(256) void fused_transpose_scatter_kernel(
    const float* __restrict__ in,
    const int* __restrict__ ht_idx,
    const int* __restrict__ sp_idx,
    const float* __restrict__ weight,
    int nvotes, int vpb) {
    __shared__ float4 tile4[32][32];    // 16 KB, [ch][swizzled hw4]
    const int t  = threadIdx.x;
    const int h0 = (blockIdx.x & 2047) * 128;
    const int r0 = (blockIdx.x >> 11) * 32;

    // Phase 1a: issue transpose global loads (512B warp runs) into registers.
    float4 v0, v1, v2, v3;
    {
        int hw4 = t & 31;
        int c0  = (t >> 5);
        v0 = *reinterpret_cast<const float4*>(&in[(size_t)(r0 + c0 +  0) * HW + h0 + hw4 * 4]);
        v1 = *reinterpret_cast<const float4*>(&in[(size_t)(r0 + c0 +  8) * HW + h0 + hw4 * 4]);
        v2 = *reinterpret_cast<const float4*>(&in[(size_t)(r0 + c0 + 16) * HW + h0 + hw4 * 4]);
        v3 = *reinterpret_cast<const float4*>(&in[(size_t)(r0 + c0 + 24) * HW + h0 + hw4 * 4]);
    }

    // Phase 1b: scatter this block's votes while the loads are in flight.
    {
        int v = blockIdx.x * vpb + t;
        if (t < vpb && v < nvotes) {
            int s   = sp_idx[v];
            int pos = atomicAdd(&g_cursor[s], 1);
            if (pos < CAP) {
                g_bucket[(size_t)s * CAP + pos] =
                    make_float2(__int_as_float(ht_idx[v]), weight[v]);
            }
        }
    }

    // Phase 1c: smem stores at XOR-swizzled column (conflict-free).
    {
        int hw4 = t & 31;
        int c0  = (t >> 5);
        tile4[c0 +  0][hw4 ^ ((((c0 +  0) >> 3) & 3) << 1)] = v0;
        tile4[c0 +  8][hw4 ^ ((((c0 +  8) >> 3) & 3) << 1)] = v1;
        tile4[c0 + 16][hw4 ^ ((((c0 + 16) >> 3) & 3) << 1)] = v2;
        tile4[c0 + 24][hw4 ^ ((((c0 + 24) >> 3) & 3) << 1)] = v3;
    }
    __syncthreads();

    // Phase 2: conflict-free scalar smem reads -> pack 8 halves ->
    // 16B global stores in 64B full-sector runs.
    const float* tf = reinterpret_cast<const float*>(tile4);
    #pragma unroll
    for (int k = 0; k < 2; k++) {
        int chg  = t & 3;                               // group of 8 channels
        int hw_l = (t >> 5) * 8 + ((t & 31) >> 2) + k * 64;
        int swz  = (chg << 1);
        int col  = ((hw_l >> 2) ^ swz) * 4 + (hw_l & 3);
        float f0 = tf[(chg * 8 + 0) * 128 + col];
        float f1 = tf[(chg * 8 + 1) * 128 + col];
        float f2 = tf[(chg * 8 + 2) * 128 + col];
        float f3 = tf[(chg * 8 + 3) * 128 + col];
        float f4 = tf[(chg * 8 + 4) * 128 + col];
        float f5 = tf[(chg * 8 + 5) * 128 + col];
        float f6 = tf[(chg * 8 + 6) * 128 + col];
        float f7 = tf[(chg * 8 + 7) * 128 + col];
        __half2 h0p = __floats2half2_rn(f0, f1);
        __half2 h1p = __floats2half2_rn(f2, f3);
        __half2 h2p = __floats2half2_rn(f4, f5);
        __half2 h3p = __floats2half2_rn(f6, f7);
        uint4 pk;
        pk.x = *reinterpret_cast<const unsigned*>(&h0p);
        pk.y = *reinterpret_cast<const unsigned*>(&h1p);
        pk.z = *reinterpret_cast<const unsigned*>(&h2p);
        pk.w = *reinterpret_cast<const unsigned*>(&h3p);
        *reinterpret_cast<uint4*>(
            &g_xTh[(size_t)(h0 + hw_l) * NCH + r0 + chg * 8]) = pk;
    }
}

// ---------------------------------------------------------------------------
// One warp per sphere bin; lane l owns channels [4l, 4l+4) in fp32 registers.
// R6-proven loop (byte-identical source): unroll-8 with float4 record loads
// (8 gathers in flight), short serial tail. 8 bins/block; smem-staged fused
// output transpose. Cursor reset ONLY in the epilogue, after the barrier —
// every warp has read its cursor before the barrier, and the store cannot
// perturb the hot loop's load batching.
__global__ __launch_bounds__(256) void accum_kernel(float* __restrict__ out) {
    const int warp = threadIdx.x >> 5;
    const int lane = threadIdx.x & 31;
    const int s    = blockIdx.x * 8 + warp;

    int n = g_cursor[s];
    if (n > CAP) n = CAP;
    const float2* __restrict__ rec  = &g_bucket[(size_t)s * CAP];
    const float4* __restrict__ rec4 = reinterpret_cast<const float4*>(rec);
    const size_t col = (size_t)(lane * 4);

    float4 a0 = make_float4(0.f, 0.f, 0.f, 0.f);
    float4 a1 = make_float4(0.f, 0.f, 0.f, 0.f);

    int i = 0;
    for (; i + 8 <= n; i += 8) {
        float4 ra = rec4[(i >> 1) + 0];
        float4 rb = rec4[(i >> 1) + 1];
        float4 rc = rec4[(i >> 1) + 2];
        float4 rd = rec4[(i >> 1) + 3];
        const uint2 p0 = *reinterpret_cast<const uint2*>(
            &g_xTh[(size_t)__float_as_int(ra.x) * NCH + col]);
        const uint2 p1 = *reinterpret_cast<const uint2*>(
            &g_xTh[(size_t)__float_as_int(ra.z) * NCH + col]);
        const uint2 p2 = *reinterpret_cast<const uint2*>(
            &g_xTh[(size_t)__float_as_int(rb.x) * NCH + col]);
        const uint2 p3 = *reinterpret_cast<const uint2*>(
            &g_xTh[(size_t)__float_as_int(rb.z) * NCH + col]);
        const uint2 p4 = *reinterpret_cast<const uint2*>(
            &g_xTh[(size_t)__float_as_int(rc.x) * NCH + col]);
        const uint2 p5 = *reinterpret_cast<const uint2*>(
            &g_xTh[(size_t)__float_as_int(rc.z) * NCH + col]);
        const uint2 p6 = *reinterpret_cast<const uint2*>(
            &g_xTh[(size_t)__float_as_int(rd.x) * NCH + col]);
        const uint2 p7 = *reinterpret_cast<const uint2*>(
            &g_xTh[(size_t)__float_as_int(rd.z) * NCH + col]);

        float2 f;
        f = __half22float2(*reinterpret_cast<const __half2*>(&p0.x));
        a0.x += f.x * ra.y; a0.y += f.y * ra.y;
        f = __half22float2(*reinterpret_cast<const __half2*>(&p0.y));
        a0.z += f.x * ra.y; a0.w += f.y * ra.y;
        f = __half22float2(*reinterpret_cast<const __half2*>(&p1.x));
        a1.x += f.x * ra.w; a1.y += f.y * ra.w;
        f = __half22float2(*reinterpret_cast<const __half2*>(&p1.y));
        a1.z += f.x * ra.w; a1.w += f.y * ra.w;

        f = __half22float2(*reinterpret_cast<const __half2*>(&p2.x));
        a0.x += f.x * rb.y; a0.y += f.y * rb.y;
        f = __half22float2(*reinterpret_cast<const __half2*>(&p2.y));
        a0.z += f.x * rb.y; a0.w += f.y * rb.y;
        f = __half22float2(*reinterpret_cast<const __half2*>(&p3.x));
        a1.x += f.x * rb.w; a1.y += f.y * rb.w;
        f = __half22float2(*reinterpret_cast<const __half2*>(&p3.y));
        a1.z += f.x * rb.w; a1.w += f.y * rb.w;

        f = __half22float2(*reinterpret_cast<const __half2*>(&p4.x));
        a0.x += f.x * rc.y; a0.y += f.y * rc.y;
        f = __half22float2(*reinterpret_cast<const __half2*>(&p4.y));
        a0.z += f.x * rc.y; a0.w += f.y * rc.y;
        f = __half22float2(*reinterpret_cast<const __half2*>(&p5.x));
        a1.x += f.x * rc.w; a1.y += f.y * rc.w;
        f = __half22float2(*reinterpret_cast<const __half2*>(&p5.y));
        a1.z += f.x * rc.w; a1.w += f.y * rc.w;

        f = __half22float2(*reinterpret_cast<const __half2*>(&p6.x));
        a0.x += f.x * rd.y; a0.y += f.y * rd.y;
        f = __half22float2(*reinterpret_cast<const __half2*>(&p6.y));
        a0.z += f.x * rd.y; a0.w += f.y * rd.y;
        f = __half22float2(*reinterpret_cast<const __half2*>(&p7.x));
        a1.x += f.x * rd.w; a1.y += f.y * rd.w;
        f = __half22float2(*reinterpret_cast<const __half2*>(&p7.y));
        a1.z += f.x * rd.w; a1.w += f.y * rd.w;
    }
    for (; i < n; i++) {
        float2 r0 = rec[i];
        const uint2 p0 = *reinterpret_cast<const uint2*>(
            &g_xTh[(size_t)__float_as_int(r0.x) * NCH + col]);
        float2 f;
        f = __half22float2(*reinterpret_cast<const __half2*>(&p0.x));
        a0.x += f.x * r0.y; a0.y += f.y * r0.y;
        f = __half22float2(*reinterpret_cast<const __half2*>(&p0.y));
        a0.z += f.x * r0.y; a0.w += f.y * r0.y;
    }
    a0.x += a1.x; a0.y += a1.y; a0.z += a1.z; a0.w += a1.w;

    // Stage [8 bins][128 ch] in smem, then write out[ch][s0..s0+7] coalesced.
    __shared__ float sm[8][128];
    *reinterpret_cast<float4*>(&sm[warp][lane * 4]) = a0;
    __syncthreads();

    if (threadIdx.x < 128) {
        const int ch = threadIdx.x;
        const int s0 = blockIdx.x * 8;
        float4 o0 = make_float4(sm[0][ch], sm[1][ch], sm[2][ch], sm[3][ch]);
        float4 o1 = make_float4(sm[4][ch], sm[5][ch], sm[6][ch], sm[7][ch]);
        float4* dst = reinterpret_cast<float4*>(&out[(size_t)ch * S + s0]);
        dst[0] = o0;
        dst[1] = o1;
    }

    // Epilogue: reset this block's 8 cursors for the next launch/replay.
    // All warps read their cursor before the __syncthreads above.
    if (threadIdx.x < 8) g_cursor[blockIdx.x * 8 + threadIdx.x] = 0;
}

// ---------------------------------------------------------------------------
extern "C" void kernel_launch(void* const* d_in, const int* in_sizes, int n_in,
                              void* d_out, int out_size) {
    const float* x      = (const float*)d_in[0];  // [128][262144] flat
    const int*   ht     = (const int*)d_in[1];
    const int*   sp     = (const int*)d_in[2];
    const float* w      = (const float*)d_in[3];
    float*       out    = (float*)d_out;          // [128][32768] flat
    const int    nvotes = in_sizes[1];

    // 1) Fused transpose+convert AND vote scatter. Cursors are guaranteed zero
    //    here: static init on first call, accum's epilogue reset afterwards.
    {
        const int nblocks = 8192;                          // (HW/128) * (NCH/32)
        const int vpb = (nvotes + nblocks - 1) / nblocks;  // 184 <= 256
        fused_transpose_scatter_kernel<<<nblocks, 256>>>(x, ht, sp, w, nvotes, vpb);
    }

    // 2) Per-bin register accumulation (R6-proven loop) + fused output
    //    transpose + epilogue cursor reset.
    accum_kernel<<<S / 8, 256>>>(out);
}

// round 12
// speedup vs baseline: 1.6167x; 1.0496x over previous
#include <cuda_runtime.h>
#include <cuda_fp16.h>

// Fixed shapes for SPHERE_CUDA_77163382440039
static constexpr int HW  = 512 * 512;   // 262144 HT cells
static constexpr int NCH = 128;         // flat channels (B4 * C4)
static constexpr int S   = 32768;       // sphere bins
static constexpr int CAP = 128;         // bucket capacity per bin (Poisson(45.8))

// Scratch (static __device__ — no runtime allocation)
__device__ __align__(16) __half g_xTh[(size_t)HW * NCH];     // x transposed [hw][ch], fp16, 67 MB
__device__ __align__(16) float2 g_bucket[(size_t)S * CAP];   // (h bits, weight) per bin, 33.5 MB
__device__ __align__(16) int g_cursor[S];

// ---------------------------------------------------------------------------
// Zero bucket cursors: int4 stores, 8192 threads.
__global__ void zero_cursor_kernel() {
    int i = blockIdx.x * blockDim.x + threadIdx.x;
    reinterpret_cast<int4*>(g_cursor)[i] = make_int4(0, 0, 0, 0);
}

// ---------------------------------------------------------------------------
// FUSED: transpose+convert (x [128][HW] fp32 -> g_xTh [HW][128] fp16) AND
// vote scatter (bucket by sphere bin). Single-use inputs (x, indices,
// weights) are read with __ldcs (evict-first) so they don't evict the
// freshly-written xT lines from L2 before accum_kernel consumes them.
// Grid: 8192 blocks x 256 thr. Transpose tile = 32 ch x 128 hw per block.
__global__ __launch_bounds__(256) void fused_transpose_scatter_kernel(
    const float* __restrict__ in,
    const int* __restrict__ ht_idx,
    const int* __restrict__ sp_idx,
    const float* __restrict__ weight,
    int nvotes, int vpb) {
    __shared__ float4 tile4[32][32];    // 16 KB, [ch][swizzled hw4]
    const int t  = threadIdx.x;
    const int h0 = (blockIdx.x & 2047) * 128;
    const int r0 = (blockIdx.x >> 11) * 32;

    // Phase 1a: issue transpose global loads (512B warp runs) into registers.
    float4 v0, v1, v2, v3;
    {
        int hw4 = t & 31;
        int c0  = (t >> 5);
        v0 = __ldcs(reinterpret_cast<const float4*>(&in[(size_t)(r0 + c0 +  0) * HW + h0 + hw4 * 4]));
        v1 = __ldcs(reinterpret_cast<const float4*>(&in[(size_t)(r0 + c0 +  8) * HW + h0 + hw4 * 4]));
        v2 = __ldcs(reinterpret_cast<const float4*>(&in[(size_t)(r0 + c0 + 16) * HW + h0 + hw4 * 4]));
        v3 = __ldcs(reinterpret_cast<const float4*>(&in[(size_t)(r0 + c0 + 24) * HW + h0 + hw4 * 4]));
    }

    // Phase 1b: scatter this block's votes while the loads are in flight.
    {
        int v = blockIdx.x * vpb + t;
        if (t < vpb && v < nvotes) {
            int s   = __ldcs(&sp_idx[v]);
            int h   = __ldcs(&ht_idx[v]);
            float wv = __ldcs(&weight[v]);
            int pos = atomicAdd(&g_cursor[s], 1);
            if (pos < CAP) {
                g_bucket[(size_t)s * CAP + pos] =
                    make_float2(__int_as_float(h), wv);
            }
        }
    }

    // Phase 1c: smem stores at XOR-swizzled column (conflict-free).
    {
        int hw4 = t & 31;
        int c0  = (t >> 5);
        tile4[c0 +  0][hw4 ^ ((((c0 +  0) >> 3) & 3) << 1)] = v0;
        tile4[c0 +  8][hw4 ^ ((((c0 +  8) >> 3) & 3) << 1)] = v1;
        tile4[c0 + 16][hw4 ^ ((((c0 + 16) >> 3) & 3) << 1)] = v2;
        tile4[c0 + 24][hw4 ^ ((((c0 + 24) >> 3) & 3) << 1)] = v3;
    }
    __syncthreads();

    // Phase 2: conflict-free scalar smem reads -> pack 8 halves ->
    // 16B global stores in 64B full-sector runs.
    const float* tf = reinterpret_cast<const float*>(tile4);
    #pragma unroll
    for (int k = 0; k < 2; k++) {
        int chg  = t & 3;                               // group of 8 channels
        int hw_l = (t >> 5) * 8 + ((t & 31) >> 2) + k * 64;
        int swz  = (chg << 1);
        int col  = ((hw_l >> 2) ^ swz) * 4 + (hw_l & 3);
        float f0 = tf[(chg * 8 + 0) * 128 + col];
        float f1 = tf[(chg * 8 + 1) * 128 + col];
        float f2 = tf[(chg * 8 + 2) * 128 + col];
        float f3 = tf[(chg * 8 + 3) * 128 + col];
        float f4 = tf[(chg * 8 + 4) * 128 + col];
        float f5 = tf[(chg * 8 + 5) * 128 + col];
        float f6 = tf[(chg * 8 + 6) * 128 + col];
        float f7 = tf[(chg * 8 + 7) * 128 + col];
        __half2 h0p = __floats2half2_rn(f0, f1);
        __half2 h1p = __floats2half2_rn(f2, f3);
        __half2 h2p = __floats2half2_rn(f4, f5);
        __half2 h3p = __floats2half2_rn(f6, f7);
        uint4 pk;
        pk.x = *reinterpret_cast<const unsigned*>(&h0p);
        pk.y = *reinterpret_cast<const unsigned*>(&h1p);
        pk.z = *reinterpret_cast<const unsigned*>(&h2p);
        pk.w = *reinterpret_cast<const unsigned*>(&h3p);
        *reinterpret_cast<uint4*>(
            &g_xTh[(size_t)(h0 + hw_l) * NCH + r0 + chg * 8]) = pk;
    }
}

// ---------------------------------------------------------------------------
// One warp per sphere bin; lane l owns channels [4l, 4l+4) in fp32 registers.
// R6/R9-proven loop (byte-identical source): unroll-8 with float4 record
// loads (8 gathers in flight), short serial tail. 8 bins/block; smem-staged
// fused output transpose. NO cursor stores anywhere in this kernel.
__global__ __launch_bounds__(256) void accum_kernel(float* __restrict__ out) {
    const int warp = threadIdx.x >> 5;
    const int lane = threadIdx.x & 31;
    const int s    = blockIdx.x * 8 + warp;

    int n = g_cursor[s];
    if (n > CAP) n = CAP;
    const float2* __restrict__ rec  = &g_bucket[(size_t)s * CAP];
    const float4* __restrict__ rec4 = reinterpret_cast<const float4*>(rec);
    const size_t col = (size_t)(lane * 4);

    float4 a0 = make_float4(0.f, 0.f, 0.f, 0.f);
    float4 a1 = make_float4(0.f, 0.f, 0.f, 0.f);

    int i = 0;
    for (; i + 8 <= n; i += 8) {
        float4 ra = rec4[(i >> 1) + 0];
        float4 rb = rec4[(i >> 1) + 1];
        float4 rc = rec4[(i >> 1) + 2];
        float4 rd = rec4[(i >> 1) + 3];
        const uint2 p0 = *reinterpret_cast<const uint2*>(
            &g_xTh[(size_t)__float_as_int(ra.x) * NCH + col]);
        const uint2 p1 = *reinterpret_cast<const uint2*>(
            &g_xTh[(size_t)__float_as_int(ra.z) * NCH + col]);
        const uint2 p2 = *reinterpret_cast<const uint2*>(
            &g_xTh[(size_t)__float_as_int(rb.x) * NCH + col]);
        const uint2 p3 = *reinterpret_cast<const uint2*>(
            &g_xTh[(size_t)__float_as_int(rb.z) * NCH + col]);
        const uint2 p4 = *reinterpret_cast<const uint2*>(
            &g_xTh[(size_t)__float_as_int(rc.x) * NCH + col]);
        const uint2 p5 = *reinterpret_cast<const uint2*>(
            &g_xTh[(size_t)__float_as_int(rc.z) * NCH + col]);
        const uint2 p6 = *reinterpret_cast<const uint2*>(
            &g_xTh[(size_t)__float_as_int(rd.x) * NCH + col]);
        const uint2 p7 = *reinterpret_cast<const uint2*>(
            &g_xTh[(size_t)__float_as_int(rd.z) * NCH + col]);

        float2 f;
        f = __half22float2(*reinterpret_cast<const __half2*>(&p0.x));
        a0.x += f.x * ra.y; a0.y += f.y * ra.y;
        f = __half22float2(*reinterpret_cast<const __half2*>(&p0.y));
        a0.z += f.x * ra.y; a0.w += f.y * ra.y;
        f = __half22float2(*reinterpret_cast<const __half2*>(&p1.x));
        a1.x += f.x * ra.w; a1.y += f.y * ra.w;
        f = __half22float2(*reinterpret_cast<const __half2*>(&p1.y));
        a1.z += f.x * ra.w; a1.w += f.y * ra.w;

        f = __half22float2(*reinterpret_cast<const __half2*>(&p2.x));
        a0.x += f.x * rb.y; a0.y += f.y * rb.y;
        f = __half22float2(*reinterpret_cast<const __half2*>(&p2.y));
        a0.z += f.x * rb.y; a0.w += f.y * rb.y;
        f = __half22float2(*reinterpret_cast<const __half2*>(&p3.x));
        a1.x += f.x * rb.w; a1.y += f.y * rb.w;
        f = __half22float2(*reinterpret_cast<const __half2*>(&p3.y));
        a1.z += f.x * rb.w; a1.w += f.y * rb.w;

        f = __half22float2(*reinterpret_cast<const __half2*>(&p4.x));
        a0.x += f.x * rc.y; a0.y += f.y * rc.y;
        f = __half22float2(*reinterpret_cast<const __half2*>(&p4.y));
        a0.z += f.x * rc.y; a0.w += f.y * rc.y;
        f = __half22float2(*reinterpret_cast<const __half2*>(&p5.x));
        a1.x += f.x * rc.w; a1.y += f.y * rc.w;
        f = __half22float2(*reinterpret_cast<const __half2*>(&p5.y));
        a1.z += f.x * rc.w; a1.w += f.y * rc.w;

        f = __half22float2(*reinterpret_cast<const __half2*>(&p6.x));
        a0.x += f.x * rd.y; a0.y += f.y * rd.y;
        f = __half22float2(*reinterpret_cast<const __half2*>(&p6.y));
        a0.z += f.x * rd.y; a0.w += f.y * rd.y;
        f = __half22float2(*reinterpret_cast<const __half2*>(&p7.x));
        a1.x += f.x * rd.w; a1.y += f.y * rd.w;
        f = __half22float2(*reinterpret_cast<const __half2*>(&p7.y));
        a1.z += f.x * rd.w; a1.w += f.y * rd.w;
    }
    for (; i < n; i++) {
        float2 r0 = rec[i];
        const uint2 p0 = *reinterpret_cast<const uint2*>(
            &g_xTh[(size_t)__float_as_int(r0.x) * NCH + col]);
        float2 f;
        f = __half22float2(*reinterpret_cast<const __half2*>(&p0.x));
        a0.x += f.x * r0.y; a0.y += f.y * r0.y;
        f = __half22float2(*reinterpret_cast<const __half2*>(&p0.y));
        a0.z += f.x * r0.y; a0.w += f.y * r0.y;
    }
    a0.x += a1.x; a0.y += a1.y; a0.z += a1.z; a0.w += a1.w;

    // Stage [8 bins][128 ch] in smem, then write out[ch][s0..s0+7] coalesced.
    __shared__ float sm[8][128];
    *reinterpret_cast<float4*>(&sm[warp][lane * 4]) = a0;
    __syncthreads();

    if (threadIdx.x < 128) {
        const int ch = threadIdx.x;
        const int s0 = blockIdx.x * 8;
        float4 o0 = make_float4(sm[0][ch], sm[1][ch], sm[2][ch], sm[3][ch]);
        float4 o1 = make_float4(sm[4][ch], sm[5][ch], sm[6][ch], sm[7][ch]);
        float4* dst = reinterpret_cast<float4*>(&out[(size_t)ch * S + s0]);
        dst[0] = o0;
        dst[1] = o1;
    }
}

// ---------------------------------------------------------------------------
extern "C" void kernel_launch(void* const* d_in, const int* in_sizes, int n_in,
                              void* d_out, int out_size) {
    const float* x      = (const float*)d_in[0];  // [128][262144] flat
    const int*   ht     = (const int*)d_in[1];
    const int*   sp     = (const int*)d_in[2];
    const float* w      = (const float*)d_in[3];
    float*       out    = (float*)d_out;          // [128][32768] flat
    const int    nvotes = in_sizes[1];

    // 1) Zero bucket cursors (S/4 = 8192 int4 stores).
    zero_cursor_kernel<<<32, 256>>>();

    // 2) Fused transpose+convert AND vote scatter (streaming loads on
    //    single-use inputs to preserve xT in L2 for accum).
    {
        const int nblocks = 8192;                          // (HW/128) * (NCH/32)
        const int vpb = (nvotes + nblocks - 1) / nblocks;  // 184 <= 256
        fused_transpose_scatter_kernel<<<nblocks, 256>>>(x, ht, sp, w, nvotes, vpb);
    }

    // 3) Per-bin register accumulation (R6/R9-proven loop) + fused output
    //    transpose.
    accum_kernel<<<S / 8, 256>>>(out);
}